// round 11
// baseline (speedup 1.0000x reference)
#include <cuda_runtime.h>
#include <math.h>

#define Bd 32
#define Sd 64
#define Hd 512
#define HH (512*512)
#define NR 2048
#define C1d 2500
#define C2d 10000
#define GRID 104
#define MAXCB 625
#define O_LOSS 2048
#define O_OUTS 2049
#define O_HF   1050625
#define O_CF   1083393
#define O_ATTN 1116161
#define O_COV  1126401
#define O_TOT  1126561

// ---------------- static device scratch ----------------
__device__ float g_topics_e[160*512];
__device__ float g_phi[160];
__device__ float g_proj[160*512];
__device__ float g_WaT[HH];
__device__ float g_WaP[5*HH];
__device__ float g_embpart[(size_t)NR*2048];
__device__ float g_T0[2048*160];
__device__ int   g_rowidx[NR];
__device__ float g_q[16384], g_h0s[16384], g_h1s[16384];
__device__ float g_cfin[32768];
__device__ float g_cov[160];
__device__ float g_scores[160];
__device__ float g_qq[5*32*512];
__device__ float g_p0[32*2048], g_p1[32*2048];
__device__ float g_outs[(size_t)NR*512];
__device__ float g_attn[Sd*32*5];
__device__ float g_hid1[NR*128];
__device__ float g_hid2[NR*32];
__device__ float g_lse[3][NR];
__device__ float g_part[(size_t)NR*MAXCB*2];
__device__ float g_outlp[NR];
__device__ unsigned g_arrive;
__device__ volatile unsigned g_release;

// ---------------- helpers ----------------
__device__ __forceinline__ float wred(float v){
#pragma unroll
  for (int o = 16; o; o >>= 1) v += __shfl_xor_sync(0xffffffffu, v, o);
  return v;
}
__device__ __forceinline__ float sigf(float x){ return 1.f/(1.f+expf(-x)); }

__device__ __forceinline__ void gsync(unsigned &gen){
  gen++;
  __threadfence();
  __syncthreads();
  if (threadIdx.x == 0){
    unsigned p = atomicAdd(&g_arrive, 1u);
    if (p == gen*GRID - 1u){ g_release = gen; }
    else { while (g_release < gen) __nanosleep(64); }
  }
  __syncthreads();
}

// ---------------- init ----------------
__global__ void k_init(const int* __restrict__ inputs, const int* __restrict__ topics,
                       const float* __restrict__ outp, const float* __restrict__ h0,
                       const float* __restrict__ cover, const float* __restrict__ emb){
  int i = blockIdx.x*blockDim.x + threadIdx.x;
  if (i == 0){ g_arrive = 0; g_release = 0; }
  if (i < 160*512){
    int row = i >> 9, e = i & 511;
    g_topics_e[i] = emb[(size_t)topics[row]*512 + e];
  }
  if (i < 16384){
    g_q[i]   = outp[i];
    g_h0s[i] = h0[i];
    g_h1s[i] = h0[16384 + i];
  }
  if (i < 160) g_cov[i] = cover[i];
  if (i < NR){ int tt = i >> 5, b = i & 31; g_rowidx[i] = inputs[b*Sd + tt]; }
}

__global__ void k_prepwa(const float* __restrict__ Wa){
  int i = blockIdx.x*blockDim.x + threadIdx.x;
  if (i < HH){
    int r = i >> 9, c = i & 511;
    g_WaT[c*512 + r] = Wa[i];
    g_WaP[i] = Wa[i];
  }
}

__global__ void k_phi(const float* __restrict__ Uf, const float* __restrict__ mask){
  int w = (blockIdx.x*blockDim.x + threadIdx.x) >> 5;
  int lane = threadIdx.x & 31;
  if (w >= 160) return;
  int b = w / 5, ii = w % 5;
  const float* te = g_topics_e + (size_t)b*5*512;
  const float* uf = Uf + (size_t)ii*5*512;
  float acc = 0.f;
  for (int j = lane; j < 2560; j += 32) acc = fmaf(te[j], uf[j], acc);
  acc = wred(acc);
  if (lane == 0){
    float ms = 0.f;
    for (int s = 0; s < Sd; s++) ms += mask[b*Sd + s];
    g_phi[b*5 + ii] = ms * (1.f/(1.f+expf(-acc)));
  }
}

__global__ void k_bias0(const float* __restrict__ b_ih0, const float* __restrict__ b_hh0){
  size_t idx = (size_t)blockIdx.x*blockDim.x + threadIdx.x;
  size_t stride = (size_t)gridDim.x*blockDim.x;
  for (; idx < (size_t)NR*2048; idx += stride){
    int j = (int)(idx & 2047);
    g_embpart[idx] += b_ih0[j] + b_hh0[j];
  }
}

// ---------------- SGEMM: C[M,N] = A[M,K] @ W[N,K]^T (opt row gather) ----------------
__global__ void __launch_bounds__(256) k_sgemm(
    const float* __restrict__ A, int lda, const float* __restrict__ W, int ldw,
    float* __restrict__ C, int ldc, int M, int N, int KK, const int* __restrict__ ridx){
  __shared__ float As[16][64];
  __shared__ float Ws[16][64];
  int tid = threadIdx.x;
  int tx = tid & 15, ty = tid >> 4;
  int row0 = blockIdx.y*64, col0 = blockIdx.x*64;
  float acc[4][4];
#pragma unroll
  for (int i=0;i<4;i++)
#pragma unroll
    for (int j=0;j<4;j++) acc[i][j] = 0.f;
  for (int k0 = 0; k0 < KK; k0 += 16){
#pragma unroll
    for (int l=0;l<4;l++){
      int lin = l*256 + tid;
      int r = lin >> 4, kk = lin & 15;
      int gr = row0 + r;
      float va = 0.f;
      if (gr < M){
        const float* ap = ridx ? (A + (size_t)ridx[gr]*lda) : (A + (size_t)gr*lda);
        va = ap[k0 + kk];
      }
      As[kk][r] = va;
      int gc = col0 + r;
      float vw = 0.f;
      if (gc < N) vw = W[(size_t)gc*ldw + k0 + kk];
      Ws[kk][r] = vw;
    }
    __syncthreads();
#pragma unroll
    for (int kk=0; kk<16; kk++){
      float a[4], b[4];
#pragma unroll
      for (int i=0;i<4;i++) a[i] = As[kk][ty*4+i];
#pragma unroll
      for (int j=0;j<4;j++) b[j] = Ws[kk][tx*4+j];
#pragma unroll
      for (int i=0;i<4;i++)
#pragma unroll
        for (int j=0;j<4;j++) acc[i][j] = fmaf(a[i], b[j], acc[i][j]);
    }
    __syncthreads();
  }
#pragma unroll
  for (int i=0;i<4;i++){
    int gr = row0 + ty*4 + i;
    if (gr >= M) continue;
#pragma unroll
    for (int j=0;j<4;j++){
      int gc = col0 + tx*4 + j;
      if (gc < N) C[(size_t)gr*ldc + gc] = acc[i][j];
    }
  }
}

// ---------------- SGEMM fused with per-row (max,sumexp) partials ----------------
__global__ void __launch_bounds__(256) k_sgemm_lse(
    const float* __restrict__ A, int lda, const float* __restrict__ W, int ldw,
    int M, int N, int KK){
  __shared__ float As[16][64];
  __shared__ float Ws[16][64];
  __shared__ float red[64][32];
  int tid = threadIdx.x;
  int tx = tid & 15, ty = tid >> 4;
  int row0 = blockIdx.y*64, col0 = blockIdx.x*64;
  float acc[4][4];
#pragma unroll
  for (int i=0;i<4;i++)
#pragma unroll
    for (int j=0;j<4;j++) acc[i][j] = 0.f;
  for (int k0 = 0; k0 < KK; k0 += 16){
#pragma unroll
    for (int l=0;l<4;l++){
      int lin = l*256 + tid;
      int r = lin >> 4, kk = lin & 15;
      int gr = row0 + r;
      float va = 0.f;
      if (gr < M) va = A[(size_t)gr*lda + k0 + kk];
      As[kk][r] = va;
      int gc = col0 + r;
      float vw = 0.f;
      if (gc < N) vw = W[(size_t)gc*ldw + k0 + kk];
      Ws[kk][r] = vw;
    }
    __syncthreads();
#pragma unroll
    for (int kk=0; kk<16; kk++){
      float a[4], b[4];
#pragma unroll
      for (int i=0;i<4;i++) a[i] = As[kk][ty*4+i];
#pragma unroll
      for (int j=0;j<4;j++) b[j] = Ws[kk][tx*4+j];
#pragma unroll
      for (int i=0;i<4;i++)
#pragma unroll
        for (int j=0;j<4;j++) acc[i][j] = fmaf(a[i], b[j], acc[i][j]);
    }
    __syncthreads();
  }
#pragma unroll
  for (int i=0;i<4;i++){
    float m = -INFINITY, s = 0.f;
#pragma unroll
    for (int j=0;j<4;j++){
      int gc = col0 + tx*4 + j;
      if (gc < N) m = fmaxf(m, acc[i][j]);
    }
#pragma unroll
    for (int j=0;j<4;j++){
      int gc = col0 + tx*4 + j;
      if (gc < N) s += expf(acc[i][j] - m);
    }
    red[ty*4+i][tx]    = m;
    red[ty*4+i][16+tx] = s;
  }
  __syncthreads();
  if (tid < 64){
    float M2 = -INFINITY;
#pragma unroll
    for (int k=0;k<16;k++) M2 = fmaxf(M2, red[tid][k]);
    float S2 = 0.f;
#pragma unroll
    for (int k=0;k<16;k++){
      float mk = red[tid][k];
      if (mk != -INFINITY) S2 += red[tid][16+k]*expf(mk - M2);
    }
    int gr = row0 + tid;
    if (gr < M){
      g_part[((size_t)gr*gridDim.x + blockIdx.x)*2]     = M2;
      g_part[((size_t)gr*gridDim.x + blockIdx.x)*2 + 1] = S2;
    }
  }
}

__global__ void k_lsemerge(int nCB, int which){
  int r = blockIdx.x;
  __shared__ float sm[128];
  int tid = threadIdx.x;
  float m = -INFINITY;
  for (int i = tid; i < nCB; i += 128) m = fmaxf(m, g_part[((size_t)r*nCB + i)*2]);
  sm[tid] = m; __syncthreads();
  for (int o = 64; o; o >>= 1){ if (tid < o) sm[tid] = fmaxf(sm[tid], sm[tid+o]); __syncthreads(); }
  float M2 = sm[0]; __syncthreads();
  float s = 0.f;
  for (int i = tid; i < nCB; i += 128){
    float mk = g_part[((size_t)r*nCB + i)*2];
    if (mk != -INFINITY) s += g_part[((size_t)r*nCB + i)*2 + 1]*expf(mk - M2);
  }
  sm[tid] = s; __syncthreads();
  for (int o = 64; o; o >>= 1){ if (tid < o) sm[tid] += sm[tid+o]; __syncthreads(); }
  if (tid == 0) g_lse[which][r] = M2 + logf(sm[0]);
}

// ---------------- persistent recurrence ----------------
__global__ void __launch_bounds__(256,1) k_recur(
    const float* __restrict__ w_hh0, const float* __restrict__ w_hh1,
    const float* __restrict__ w_ih1, const float* __restrict__ b_ih1,
    const float* __restrict__ b_hh1, const float* __restrict__ va_w,
    const float* __restrict__ va_b, const float* __restrict__ c0in){
  extern __shared__ float sx[];          // [512][33] transposed x
  __shared__ float salpha[32][5];
  int tid = threadIdx.x, lane = tid & 31, warp = tid >> 5, bx = blockIdx.x;
  int gid = bx*8 + warp;
  unsigned gen = 0;
  float creg0 = 0.f, creg1 = 0.f;
  int jC = bx + 104*warp;                // C/D unit (h-index), valid if <512

  const float* stagesrc;
  if (bx < 40) stagesrc = g_q;
  else if (bx < 72) stagesrc = g_h0s;
  else stagesrc = g_h1s;

  int c0a;
  if (gid < 320) c0a = gid*8;
  else if (gid < 576) c0a = (gid-320)*8;
  else c0a = (gid-576)*8;

  for (int t = 0; t < Sd; t++){
    // ---- phase A: qq (5x512 cols), p0 (2048), p1 (2048) ----
    for (int i2 = tid; i2 < 16384; i2 += 256){
      int b2 = i2 >> 9, k2 = i2 & 511;
      sx[k2*33 + b2] = __ldcg(stagesrc + i2);
    }
    __syncthreads();
    {
      const float* W; float* ob;
      if (gid < 320){
        int ii = c0a >> 9, jj = c0a & 511;
        W = g_WaP + (size_t)ii*HH + (size_t)jj*512;
        ob = g_qq + (size_t)(ii*32 + lane)*512 + jj;
      } else if (gid < 576){
        W = w_hh0 + (size_t)c0a*512;
        ob = g_p0 + lane*2048 + c0a;
      } else {
        W = w_hh1 + (size_t)c0a*512;
        ob = g_p1 + lane*2048 + c0a;
      }
      float acc[8] = {0,0,0,0,0,0,0,0};
      for (int k0 = 0; k0 < 512; k0 += 4){
        float x0 = sx[k0*33+lane], x1 = sx[(k0+1)*33+lane];
        float x2 = sx[(k0+2)*33+lane], x3 = sx[(k0+3)*33+lane];
#pragma unroll
        for (int r = 0; r < 8; r++){
          float4 wv = *(const float4*)(W + (size_t)r*512 + k0);
          acc[r] = fmaf(wv.x,x0,fmaf(wv.y,x1,fmaf(wv.z,x2,fmaf(wv.w,x3,acc[r]))));
        }
      }
#pragma unroll
      for (int r = 0; r < 8; r++) ob[r] = acc[r];
    }
    gsync(gen);
    // ---- phase B: scores ----
    if (gid < 160){
      int b = gid/5, ii = gid%5;
      const float* qq = g_qq + (size_t)(ii*32 + b)*512;
      const float* pk = g_proj + (size_t)(b*5 + ii)*512;
      float acc = 0.f;
      for (int h = lane; h < 512; h += 32)
        acc = fmaf(va_w[h], tanhf(__ldcg(qq+h) + pk[h]), acc);
      acc = wred(acc);
      if (lane == 0) g_scores[b*5+ii] = (acc + va_b[0]) * __ldcg(g_cov + b*5 + ii);
    }
    gsync(gen);
    // ---- phase C: softmax, cov/attn, LSTM0 (mt folded via T0) ----
    if (warp == 0){
      float sc[5], m = -1e30f;
#pragma unroll
      for (int i5 = 0; i5 < 5; i5++){ sc[i5] = __ldcg(g_scores + lane*5 + i5); m = fmaxf(m, sc[i5]); }
      float s = 0.f;
#pragma unroll
      for (int i5 = 0; i5 < 5; i5++){ sc[i5] = expf(sc[i5]-m); s += sc[i5]; }
#pragma unroll
      for (int i5 = 0; i5 < 5; i5++){
        float a = sc[i5]/s;
        salpha[lane][i5] = a;
        if (bx == 0){
          g_attn[(t*32 + lane)*5 + i5] = a;
          g_cov[lane*5 + i5] = __ldcg(g_cov + lane*5 + i5) - a/g_phi[lane*5 + i5];
        }
      }
    }
    __syncthreads();
    if (jC < 512){
      size_t row = (size_t)(t*32 + lane);
      float a0 = salpha[lane][0], a1 = salpha[lane][1], a2 = salpha[lane][2];
      float a3 = salpha[lane][3], a4 = salpha[lane][4];
      float gv[4];
#pragma unroll
      for (int gi = 0; gi < 4; gi++){
        int col = gi*512 + jC;
        const float* t0 = g_T0 + (size_t)col*160 + lane*5;
        float v = __ldcg(g_embpart + row*2048 + col) + __ldcg(g_p0 + lane*2048 + col);
        v = fmaf(a0,t0[0],v); v = fmaf(a1,t0[1],v); v = fmaf(a2,t0[2],v);
        v = fmaf(a3,t0[3],v); v = fmaf(a4,t0[4],v);
        gv[gi] = v;
      }
      float cp = (t == 0) ? c0in[lane*512 + jC] : creg0;
      float cn = sigf(gv[1])*cp + sigf(gv[0])*tanhf(gv[2]);
      creg0 = cn;
      g_h0s[lane*512 + jC] = sigf(gv[3])*tanhf(cn);
      if (t == Sd-1) g_cfin[lane*512 + jC] = cn;
    }
    gsync(gen);
    // ---- phase D: LSTM1 (h0n @ w_ih1 + p1) ----
    for (int i2 = tid; i2 < 16384; i2 += 256){
      int b2 = i2 >> 9, k2 = i2 & 511;
      sx[k2*33 + b2] = __ldcg(g_h0s + i2);
    }
    __syncthreads();
    if (jC < 512){
      float acc[4] = {0,0,0,0};
      const float* W = w_ih1 + (size_t)jC*512;
      for (int k0 = 0; k0 < 512; k0 += 4){
        float x0 = sx[k0*33+lane], x1 = sx[(k0+1)*33+lane];
        float x2 = sx[(k0+2)*33+lane], x3 = sx[(k0+3)*33+lane];
#pragma unroll
        for (int gi = 0; gi < 4; gi++){
          float4 wv = *(const float4*)(W + (size_t)gi*512*512 + k0);
          acc[gi] = fmaf(wv.x,x0,fmaf(wv.y,x1,fmaf(wv.z,x2,fmaf(wv.w,x3,acc[gi]))));
        }
      }
#pragma unroll
      for (int gi = 0; gi < 4; gi++){
        int col = gi*512 + jC;
        acc[gi] += __ldcg(g_p1 + lane*2048 + col) + b_ih1[col] + b_hh1[col];
      }
      float cp = (t == 0) ? c0in[16384 + lane*512 + jC] : creg1;
      float cn = sigf(acc[1])*cp + sigf(acc[0])*tanhf(acc[2]);
      creg1 = cn;
      float hn = sigf(acc[3])*tanhf(cn);
      g_h1s[lane*512 + jC] = hn;
      g_q[lane*512 + jC] = hn;
      g_outs[(size_t)(t*32 + lane)*512 + jC] = hn;
      if (t == Sd-1) g_cfin[16384 + lane*512 + jC] = cn;
    }
    gsync(gen);
  }
}

// ---------------- final log-probs ----------------
__global__ void k_final(const int* __restrict__ target, const float* __restrict__ head_w,
                        const float* __restrict__ t1_w2, const float* __restrict__ t2_w2,
                        float* out, int out_size){
  int warp = threadIdx.x >> 5, lane = threadIdx.x & 31;
  int n = blockIdx.x*8 + warp;
  if (n >= NR) return;
  int b = n & 31, s = n >> 5;
  int tgt = target[b*Sd + s];
  const float* x = g_outs + (size_t)n*512;
  int csel = (tgt < C1d) ? tgt : ((tgt < C2d) ? C1d : C1d+1);
  float d = 0.f;
  const float* hw = head_w + (size_t)csel*512;
  for (int k = lane; k < 512; k += 32) d = fmaf(x[k], hw[k], d);
  d = wred(d);
  float lp;
  if (tgt < C1d){
    lp = d - g_lse[0][n];
  } else if (tgt < C2d){
    const float* h1 = g_hid1 + (size_t)n*128;
    const float* w2 = t1_w2 + (size_t)(tgt - C1d)*128;
    float d2 = 0.f;
    for (int k = lane; k < 128; k += 32) d2 = fmaf(h1[k], w2[k], d2);
    d2 = wred(d2);
    lp = (d - g_lse[0][n]) + (d2 - g_lse[1][n]);
  } else {
    const float* h2 = g_hid2 + (size_t)n*32;
    const float* w2 = t2_w2 + (size_t)(tgt - C2d)*32;
    float d2 = h2[lane]*w2[lane];
    d2 = wred(d2);
    lp = (d - g_lse[0][n]) + (d2 - g_lse[2][n]);
  }
  if (lane == 0){
    g_outlp[n] = lp;
    if (n < out_size) out[n] = lp;
  }
}

__global__ void k_loss(float* out, int out_size){
  __shared__ float sm[256];
  float s = 0.f;
  for (int i = threadIdx.x; i < NR; i += 256) s += g_outlp[i];
  sm[threadIdx.x] = s; __syncthreads();
  for (int o = 128; o; o >>= 1){ if (threadIdx.x < o) sm[threadIdx.x] += sm[threadIdx.x+o]; __syncthreads(); }
  if (threadIdx.x == 0 && O_LOSS < out_size) out[O_LOSS] = -sm[0]/(float)NR;
}

__global__ void k_copy(float* out, int out_size){
  int idx = blockIdx.x*256 + threadIdx.x + O_OUTS;
  if (idx >= out_size || idx >= O_TOT) return;
  float v;
  if (idx < O_HF) v = g_outs[idx - O_OUTS];
  else if (idx < O_CF){ int o = idx - O_HF; v = (o < 16384) ? g_h0s[o] : g_h1s[o - 16384]; }
  else if (idx < O_ATTN) v = g_cfin[idx - O_CF];
  else if (idx < O_COV) v = g_attn[idx - O_ATTN];
  else v = g_cov[idx - O_COV];
  out[idx] = v;
}

// ---------------- launch ----------------
extern "C" void kernel_launch(void* const* d_in, const int* in_sizes, int n_in,
                              void* d_out, int out_size){
  const int*   inputs = (const int*)d_in[0];
  const int*   topics = (const int*)d_in[1];
  const float* output = (const float*)d_in[2];
  const float* h0     = (const float*)d_in[3];
  const float* c0     = (const float*)d_in[4];
  const float* mask   = (const float*)d_in[5];
  const int*   target = (const int*)d_in[6];
  const float* cover  = (const float*)d_in[7];
  const float* emb_w  = (const float*)d_in[8];
  const float* Uf_w   = (const float*)d_in[9];
  const float* Ua_w   = (const float*)d_in[10];
  const float* Wa_w   = (const float*)d_in[11];
  const float* va_w   = (const float*)d_in[12];
  const float* va_b   = (const float*)d_in[13];
  const float* w_ih0  = (const float*)d_in[14];
  const float* w_hh0  = (const float*)d_in[15];
  const float* b_ih0  = (const float*)d_in[16];
  const float* b_hh0  = (const float*)d_in[17];
  const float* w_ih1  = (const float*)d_in[18];
  const float* w_hh1  = (const float*)d_in[19];
  const float* b_ih1  = (const float*)d_in[20];
  const float* b_hh1  = (const float*)d_in[21];
  const float* head_w = (const float*)d_in[22];
  const float* t1_w1  = (const float*)d_in[23];
  const float* t1_w2  = (const float*)d_in[24];
  const float* t2_w1  = (const float*)d_in[25];
  const float* t2_w2  = (const float*)d_in[26];
  float* out = (float*)d_out;

  float *pWaT, *pWaP, *pTe, *pProj, *pEmbp, *pT0, *pOuts, *pH1, *pH2;
  int* pRid;
  cudaGetSymbolAddress((void**)&pWaT, g_WaT);
  cudaGetSymbolAddress((void**)&pWaP, g_WaP);
  cudaGetSymbolAddress((void**)&pTe,  g_topics_e);
  cudaGetSymbolAddress((void**)&pProj,g_proj);
  cudaGetSymbolAddress((void**)&pEmbp,g_embpart);
  cudaGetSymbolAddress((void**)&pT0,  g_T0);
  cudaGetSymbolAddress((void**)&pOuts,g_outs);
  cudaGetSymbolAddress((void**)&pH1,  g_hid1);
  cudaGetSymbolAddress((void**)&pH2,  g_hid2);
  cudaGetSymbolAddress((void**)&pRid, g_rowidx);

  cudaFuncSetAttribute(k_recur, cudaFuncAttributeMaxDynamicSharedMemorySize, 69632);

  k_init<<<320, 256>>>(inputs, topics, output, h0, cover, emb_w);
  k_prepwa<<<1024, 256>>>(Wa_w);
  k_phi<<<20, 256>>>(Uf_w, mask);
  // Wa powers: WaP[i+1] = WaP[i] @ Wa  (W = Wa^T so W^T = Wa)
  for (int i = 0; i < 4; i++)
    k_sgemm<<<dim3(8,8), 256>>>(pWaP + (size_t)i*HH, 512, pWaT, 512,
                                pWaP + (size_t)(i+1)*HH, 512, 512, 512, 512, nullptr);
  // proj_keys
  k_sgemm<<<dim3(8,3), 256>>>(pTe, 512, Ua_w, 512, pProj, 512, 160, 512, 512, nullptr);
  // embpart = gathered emb @ w_ih0[:, :512]^T
  k_sgemm<<<dim3(32,32), 256>>>(emb_w, 512, w_ih0, 1024, pEmbp, 2048, 2048, 2048, 512, pRid);
  k_bias0<<<2048, 256>>>(b_ih0, b_hh0);
  // T0 = w_ih0[:, 512:] @ topics_e^T
  k_sgemm<<<dim3(3,32), 256>>>(w_ih0 + 512, 1024, pTe, 512, pT0, 160, 2048, 160, 512, nullptr);
  // recurrence
  k_recur<<<GRID, 256, 67584>>>(w_hh0, w_hh1, w_ih1, b_ih1, b_hh1, va_w, va_b, c0);
  // adaptive softmax head
  k_sgemm<<<dim3(2,32), 256>>>(pOuts, 512, t1_w1, 512, pH1, 128, 2048, 128, 512, nullptr);
  k_sgemm<<<dim3(1,32), 256>>>(pOuts, 512, t2_w1, 512, pH2, 32, 2048, 32, 512, nullptr);
  k_sgemm_lse<<<dim3(40,32), 256>>>(pOuts, 512, head_w, 512, 2048, 2502, 512);
  k_lsemerge<<<2048, 128>>>(40, 0);
  k_sgemm_lse<<<dim3(118,32), 256>>>(pH1, 128, t1_w2, 128, 2048, 7500, 128);
  k_lsemerge<<<2048, 128>>>(118, 1);
  k_sgemm_lse<<<dim3(625,32), 256>>>(pH2, 32, t2_w2, 32, 2048, 40000, 32);
  k_lsemerge<<<2048, 128>>>(625, 2);
  k_final<<<256, 256>>>(target, head_w, t1_w2, t2_w2, out, out_size);
  k_loss<<<1, 256>>>(out, out_size);
  k_copy<<<(O_TOT - O_OUTS + 255)/256, 256>>>(out, out_size);
}

// round 13
// speedup vs baseline: 1.0721x; 1.0721x over previous
#include <cuda_runtime.h>
#include <math.h>

#define GRID 128
#define HH (512*512)
#define NR 2048
#define C1d 2500
#define C2d 10000
#define MAXCB 313
#define O_LOSS 2048
#define O_OUTS 2049
#define O_HF   1050625
#define O_CF   1083393
#define O_ATTN 1116161
#define O_COV  1126401
#define O_TOT  1126561
#define PIT 132

typedef unsigned long long ull;

// ---------------- static device scratch ----------------
__device__ float g_topics_e[160*512];
__device__ float g_phi[160];
__device__ float g_proj[160*512];
__device__ float g_projT[2560*32];
__device__ float g_WaT[HH];
__device__ float g_WaP[(2560+8)*512];
__device__ float g_whh0p[(2048+8)*512];
__device__ float g_whh1p[(2048+8)*512];
__device__ float g_embpart[(size_t)NR*2048];
__device__ float g_T0[2048*160];
__device__ int   g_rowidx[NR];
__device__ float g_q[16384], g_h0s[16384], g_h1s[16384];
__device__ float g_cfin[32768];
__device__ float g_cov[320];              // double-buffered by step parity
__device__ ull   g_scoresI[160];          // fixed-point score accumulators
__device__ float g_p[4096*32];            // p0 rows 0..2047, p1 rows 2048..4095
__device__ float g_outs[(size_t)NR*512];
__device__ float g_attn[64*32*5];
__device__ float g_hid1[NR*128];
__device__ float g_hid2[NR*32];
__device__ float g_lse[3][NR];
__device__ float g_part[(size_t)NR*MAXCB*2];
__device__ float g_outlp[NR];
__device__ unsigned g_arrive;
__device__ volatile unsigned g_release;

// ---------------- helpers ----------------
__device__ __forceinline__ float wred(float v){
#pragma unroll
  for (int o = 16; o; o >>= 1) v += __shfl_xor_sync(0xffffffffu, v, o);
  return v;
}
__device__ __forceinline__ float sigf(float x){ return 1.f/(1.f+expf(-x)); }

__device__ __forceinline__ ull pk2(float a){
  ull r; unsigned u = __float_as_uint(a);
  asm("mov.b64 %0, {%1, %1};" : "=l"(r) : "r"(u));
  return r;
}
__device__ __forceinline__ ull ff2(ull a, ull b, ull c){
  ull d;
  asm("fma.rn.f32x2 %0, %1, %2, %3;" : "=l"(d) : "l"(a), "l"(b), "l"(c));
  return d;
}
__device__ __forceinline__ float upsum(ull v){
  float lo = __uint_as_float((unsigned)(v & 0xffffffffull));
  float hi = __uint_as_float((unsigned)(v >> 32));
  return lo + hi;
}

__device__ __forceinline__ void gsync(unsigned &gen){
  gen++;
  __threadfence();
  __syncthreads();
  if (threadIdx.x == 0){
    unsigned p = atomicAdd(&g_arrive, 1u);
    if (p == gen*GRID - 1u){ g_release = gen; }
    else { while (g_release < gen) __nanosleep(64); }
  }
  __syncthreads();
}

// ---------------- init ----------------
__global__ void k_init(const int* __restrict__ inputs, const int* __restrict__ topics,
                       const float* __restrict__ outp, const float* __restrict__ h0,
                       const float* __restrict__ cover, const float* __restrict__ emb){
  int i = blockIdx.x*blockDim.x + threadIdx.x;
  if (i == 0){ g_arrive = 0; g_release = 0; }
  if (i < 160*512){
    int row = i >> 9, e = i & 511;
    g_topics_e[i] = emb[(size_t)topics[row]*512 + e];
  }
  if (i < 16384){
    g_q[i]   = outp[i];
    g_h0s[i] = h0[i];
    g_h1s[i] = h0[16384 + i];
  }
  if (i < 160){ g_cov[i] = cover[i]; g_scoresI[i] = 0ull; }
  if (i < NR){ int tt = i >> 5, b = i & 31; g_rowidx[i] = inputs[b*64 + tt]; }
}

__global__ void k_prepwa(const float* __restrict__ Wa){
  int i = blockIdx.x*blockDim.x + threadIdx.x;
  if (i < HH){
    int r = i >> 9, c = i & 511;
    g_WaT[c*512 + r] = Wa[i];
    g_WaP[i] = Wa[i];
  }
}

__global__ void k_prepwh(const float* __restrict__ w0, const float* __restrict__ w1){
  int i = blockIdx.x*blockDim.x + threadIdx.x;
  if (i < HH*4){ g_whh0p[i] = w0[i]; g_whh1p[i] = w1[i]; }
}

__global__ void k_projT(){
  int idx = blockIdx.x*blockDim.x + threadIdx.x;
  if (idx < 2560*32){
    int b = idx & 31, rh = idx >> 5;
    int i = rh >> 9, h = rh & 511;
    g_projT[idx] = g_proj[(b*5 + i)*512 + h];
  }
}

__global__ void k_phi(const float* __restrict__ Uf, const float* __restrict__ mask){
  int w = (blockIdx.x*blockDim.x + threadIdx.x) >> 5;
  int lane = threadIdx.x & 31;
  if (w >= 160) return;
  int b = w / 5, ii = w % 5;
  const float* te = g_topics_e + (size_t)b*5*512;
  const float* uf = Uf + (size_t)ii*5*512;
  float acc = 0.f;
  for (int j = lane; j < 2560; j += 32) acc = fmaf(te[j], uf[j], acc);
  acc = wred(acc);
  if (lane == 0){
    float ms = 0.f;
    for (int s = 0; s < 64; s++) ms += mask[b*64 + s];
    g_phi[b*5 + ii] = ms * (1.f/(1.f+expf(-acc)));
  }
}

__global__ void k_bias0(const float* __restrict__ b_ih0, const float* __restrict__ b_hh0){
  size_t idx = (size_t)blockIdx.x*blockDim.x + threadIdx.x;
  size_t stride = (size_t)gridDim.x*blockDim.x;
  for (; idx < (size_t)NR*2048; idx += stride){
    int j = (int)(idx & 2047);
    g_embpart[idx] += b_ih0[j] + b_hh0[j];
  }
}

// ---------------- 128x128 SGEMM (f32x2), optionally fused LSE partials ----------------
// C[M,N] = A[M,K] @ W[N,K]^T ; LSE=true writes per-(row,colblock) (max,sumexp) to g_part
template<bool LSE>
__global__ void __launch_bounds__(256) k_mm128(
    const float* __restrict__ A, int lda, const float* __restrict__ W, int ldw,
    float* __restrict__ C, int ldc, int M, int N, int KK, const int* __restrict__ ridx){
  __shared__ float sm[2*16*PIT];
  float* As = sm;
  float* Bs = sm + 16*PIT;
  int tid = threadIdx.x;
  int tx = tid & 15, ty = tid >> 4;
  int row0 = blockIdx.y*128, col0 = blockIdx.x*128;

  // hoist staging pointers
  const float* ap[2]; const float* wp[2]; bool af[2], wf[2]; int kqh[2]; int rh[2];
#pragma unroll
  for (int l = 0; l < 2; l++){
    int id = l*256 + tid;
    int r = id >> 2;
    kqh[l] = (id & 3)*4;
    rh[l] = r;
    int gr = row0 + r;
    af[l] = (gr < M);
    ap[l] = af[l] ? (ridx ? (A + (size_t)ridx[gr]*lda) : (A + (size_t)gr*lda)) : A;
    int gc = col0 + r;
    wf[l] = (gc < N);
    wp[l] = wf[l] ? (W + (size_t)gc*ldw) : W;
  }

  ull acc2[8][4];
#pragma unroll
  for (int i = 0; i < 8; i++)
#pragma unroll
    for (int j = 0; j < 4; j++) acc2[i][j] = 0ull;

  for (int k0 = 0; k0 < KK; k0 += 16){
#pragma unroll
    for (int l = 0; l < 2; l++){
      float4 va = make_float4(0.f,0.f,0.f,0.f);
      if (af[l]) va = *(const float4*)(ap[l] + k0 + kqh[l]);
      As[(kqh[l]+0)*PIT + rh[l]] = va.x;
      As[(kqh[l]+1)*PIT + rh[l]] = va.y;
      As[(kqh[l]+2)*PIT + rh[l]] = va.z;
      As[(kqh[l]+3)*PIT + rh[l]] = va.w;
      float4 vb = make_float4(0.f,0.f,0.f,0.f);
      if (wf[l]) vb = *(const float4*)(wp[l] + k0 + kqh[l]);
      Bs[(kqh[l]+0)*PIT + rh[l]] = vb.x;
      Bs[(kqh[l]+1)*PIT + rh[l]] = vb.y;
      Bs[(kqh[l]+2)*PIT + rh[l]] = vb.z;
      Bs[(kqh[l]+3)*PIT + rh[l]] = vb.w;
    }
    __syncthreads();
#pragma unroll
    for (int kk = 0; kk < 16; kk++){
      float4 a0 = *(const float4*)&As[kk*PIT + ty*8];
      float4 a1 = *(const float4*)&As[kk*PIT + ty*8 + 4];
      ulonglong2 b0 = *(const ulonglong2*)&Bs[kk*PIT + tx*8];
      ulonglong2 b1 = *(const ulonglong2*)&Bs[kk*PIT + tx*8 + 4];
      float av[8] = {a0.x,a0.y,a0.z,a0.w,a1.x,a1.y,a1.z,a1.w};
      ull bv[4] = {b0.x, b0.y, b1.x, b1.y};
#pragma unroll
      for (int i = 0; i < 8; i++){
        ull a2 = pk2(av[i]);
#pragma unroll
        for (int j = 0; j < 4; j++) acc2[i][j] = ff2(a2, bv[j], acc2[i][j]);
      }
    }
    __syncthreads();
  }

  if (!LSE){
#pragma unroll
    for (int i = 0; i < 8; i++){
      int gr = row0 + ty*8 + i;
      if (gr >= M) continue;
#pragma unroll
      for (int j = 0; j < 4; j++){
        int gc = col0 + tx*8 + j*2;
        float lo = __uint_as_float((unsigned)(acc2[i][j] & 0xffffffffull));
        float hi = __uint_as_float((unsigned)(acc2[i][j] >> 32));
        if (gc     < N) C[(size_t)gr*ldc + gc]     = lo;
        if (gc + 1 < N) C[(size_t)gr*ldc + gc + 1] = hi;
      }
    }
  } else {
    float* red = sm;   // reuse tiles: 128 rows x 32 floats = 4096 <= 4224
#pragma unroll
    for (int i = 0; i < 8; i++){
      float m = -INFINITY, s = 0.f;
      float vals[8];
#pragma unroll
      for (int j = 0; j < 4; j++){
        vals[2*j]   = __uint_as_float((unsigned)(acc2[i][j] & 0xffffffffull));
        vals[2*j+1] = __uint_as_float((unsigned)(acc2[i][j] >> 32));
      }
#pragma unroll
      for (int j = 0; j < 8; j++){
        int gc = col0 + tx*8 + j;
        if (gc < N) m = fmaxf(m, vals[j]);
      }
#pragma unroll
      for (int j = 0; j < 8; j++){
        int gc = col0 + tx*8 + j;
        if (gc < N) s += expf(vals[j] - m);
      }
      red[(ty*8+i)*32 + tx]      = m;
      red[(ty*8+i)*32 + 16 + tx] = s;
    }
    __syncthreads();
    if (tid < 128){
      float M2 = -INFINITY;
#pragma unroll
      for (int k = 0; k < 16; k++) M2 = fmaxf(M2, red[tid*32 + k]);
      float S2 = 0.f;
#pragma unroll
      for (int k = 0; k < 16; k++){
        float mk = red[tid*32 + k];
        if (mk != -INFINITY) S2 += red[tid*32 + 16 + k]*expf(mk - M2);
      }
      int gr = row0 + tid;
      if (gr < M){
        g_part[((size_t)gr*gridDim.x + blockIdx.x)*2]     = M2;
        g_part[((size_t)gr*gridDim.x + blockIdx.x)*2 + 1] = S2;
      }
    }
  }
}

__global__ void k_lsemerge(int nCB, int which){
  int r = blockIdx.x;
  __shared__ float sm[128];
  int tid = threadIdx.x;
  float m = -INFINITY;
  for (int i = tid; i < nCB; i += 128) m = fmaxf(m, g_part[((size_t)r*nCB + i)*2]);
  sm[tid] = m; __syncthreads();
  for (int o = 64; o; o >>= 1){ if (tid < o) sm[tid] = fmaxf(sm[tid], sm[tid+o]); __syncthreads(); }
  float M2 = sm[0]; __syncthreads();
  float s = 0.f;
  for (int i = tid; i < nCB; i += 128){
    float mk = g_part[((size_t)r*nCB + i)*2];
    if (mk != -INFINITY) s += g_part[((size_t)r*nCB + i)*2 + 1]*expf(mk - M2);
  }
  sm[tid] = s; __syncthreads();
  for (int o = 64; o; o >>= 1){ if (tid < o) sm[tid] += sm[tid+o]; __syncthreads(); }
  if (tid == 0) g_lse[which][r] = M2 + logf(sm[0]);
}

// ---------------- persistent recurrence ----------------
// 3 barriers/step: A(matvecs+fused scores) | C(softmax+LSTM0) | D(LSTM1)
__global__ void __launch_bounds__(256,1) k_recur(
    const float* __restrict__ w_ih1, const float* __restrict__ b_ih1,
    const float* __restrict__ b_hh1, const float* __restrict__ va_w,
    const float* __restrict__ va_b, const float* __restrict__ c0in){
  extern __shared__ float sx[];     // 256 k2-pairs x 33 x (2 floats) = 16896 floats
  __shared__ float salpha[32][5];
  int tid = threadIdx.x, lane = tid & 31, warp = tid >> 5, bx = blockIdx.x;
  unsigned gen = 0;
  float creg0 = 0.f, creg1 = 0.f;
  int jC = (warp < 4) ? (bx + 128*warp) : -1;

  // region setup for phase A
  int region, NW, R, lb;
  if (bx < 50){ region = 0; lb = bx;      NW = 400; R = 2560; }
  else if (bx < 89){ region = 1; lb = bx - 50; NW = 312; R = 2048; }
  else { region = 2; lb = bx - 89; NW = 312; R = 2048; }
  int g  = lb*8 + warp;
  int r0 = (int)(((long long)R*g)/NW);
  int r1 = (int)(((long long)R*(g+1))/NW);
  int nr = r1 - r0;                 // 6 or 7
  const float* Wbase = (region == 0) ? (g_WaP + (size_t)r0*512)
                     : (region == 1) ? (g_whh0p + (size_t)r0*512)
                                     : (g_whh1p + (size_t)r0*512);
  const ull* xq = (const ull*)sx;

  for (int t = 0; t < 64; t++){
    // ---- stage x (paired-transposed) ----
    const float* xsrc = (region == 0) ? g_q : (region == 1 ? g_h0s : g_h1s);
    for (int i2 = tid; i2 < 16384; i2 += 256){
      int b2 = i2 >> 9, k = i2 & 511;
      sx[(k>>1)*66 + b2*2 + (k&1)] = __ldcg(xsrc + i2);
    }
    __syncthreads();
    // ---- phase A: 7-row x 32-batch matvec, f32x2 ----
    {
      ull acc2[7];
#pragma unroll
      for (int r = 0; r < 7; r++) acc2[r] = 0ull;
#pragma unroll 2
      for (int p = 0; p < 256; p += 2){
        ull xa = xq[p*33 + lane];
        ull xb = xq[(p+1)*33 + lane];
#pragma unroll
        for (int r = 0; r < 7; r++){
          ulonglong2 wv = *(const ulonglong2*)(Wbase + (size_t)r*512 + (p<<1));
          acc2[r] = ff2(wv.x, xa, acc2[r]);
          acc2[r] = ff2(wv.y, xb, acc2[r]);
        }
      }
      if (region == 0){
        float partial = 0.f; int icur = r0 >> 9;
#pragma unroll
        for (int r = 0; r < 7; r++){
          if (r >= nr) break;
          int row = r0 + r;
          int i = row >> 9, h = row & 511;
          if (i != icur){
            atomicAdd(&g_scoresI[lane*5 + icur],
                      (ull)(long long)__float2ll_rn(partial * 4294967296.f));
            partial = 0.f; icur = i;
          }
          float a = upsum(acc2[r]);
          partial = fmaf(va_w[h], tanhf(a + g_projT[(size_t)row*32 + lane]), partial);
        }
        atomicAdd(&g_scoresI[lane*5 + icur],
                  (ull)(long long)__float2ll_rn(partial * 4294967296.f));
      } else {
        int base = (region == 1) ? 0 : 2048;
#pragma unroll
        for (int r = 0; r < 7; r++){
          if (r >= nr) break;
          g_p[(size_t)(base + r0 + r)*32 + lane] = upsum(acc2[r]);
        }
      }
    }
    gsync(gen);  // barrier 1

    // ---- phase C: softmax + cov/attn + LSTM0 ----
    if (warp == 0){
      int pb = (t & 1)*160;
      float vb0 = va_b[0];
      float sc[5], m = -1e30f;
      float covv[5];
#pragma unroll
      for (int i5 = 0; i5 < 5; i5++){
        long long sv = (long long)__ldcg(&g_scoresI[lane*5 + i5]);
        covv[i5] = __ldcg(g_cov + pb + lane*5 + i5);
        sc[i5] = ((float)sv * 2.3283064365386963e-10f + vb0) * covv[i5];
        m = fmaxf(m, sc[i5]);
      }
      float s = 0.f;
#pragma unroll
      for (int i5 = 0; i5 < 5; i5++){ sc[i5] = expf(sc[i5]-m); s += sc[i5]; }
      int qb = 160 - pb;
#pragma unroll
      for (int i5 = 0; i5 < 5; i5++){
        float a = sc[i5]/s;
        salpha[lane][i5] = a;
        if (bx == 0){
          g_attn[(t*32 + lane)*5 + i5] = a;
          g_cov[qb + lane*5 + i5] = covv[i5] - a/g_phi[lane*5 + i5];
        }
      }
    }
    __syncthreads();
    if (jC >= 0){
      size_t row = (size_t)(t*32 + lane);
      float a0 = salpha[lane][0], a1 = salpha[lane][1], a2 = salpha[lane][2];
      float a3 = salpha[lane][3], a4 = salpha[lane][4];
      float gv[4];
#pragma unroll
      for (int gi = 0; gi < 4; gi++){
        int col = gi*512 + jC;
        const float* t0 = g_T0 + (size_t)col*160 + lane*5;
        float v = g_embpart[row*2048 + col] + __ldcg(g_p + (size_t)col*32 + lane);
        v = fmaf(a0,t0[0],v); v = fmaf(a1,t0[1],v); v = fmaf(a2,t0[2],v);
        v = fmaf(a3,t0[3],v); v = fmaf(a4,t0[4],v);
        gv[gi] = v;
      }
      float cp = (t == 0) ? c0in[lane*512 + jC] : creg0;
      float cn = sigf(gv[1])*cp + sigf(gv[0])*tanhf(gv[2]);
      creg0 = cn;
      g_h0s[lane*512 + jC] = sigf(gv[3])*tanhf(cn);
      if (t == 63) g_cfin[lane*512 + jC] = cn;
    }
    gsync(gen);  // barrier 2

    // ---- phase D: LSTM1 ----
    if (bx == 0 && warp == 4){
      for (int i = lane; i < 160; i += 32) g_scoresI[i] = 0ull;
    }
    for (int i2 = tid; i2 < 16384; i2 += 256){
      int b2 = i2 >> 9, k = i2 & 511;
      sx[(k>>1)*66 + b2*2 + (k&1)] = __ldcg(g_h0s + i2);
    }
    __syncthreads();
    if (jC >= 0){
      ull acc2[4];
#pragma unroll
      for (int gi = 0; gi < 4; gi++) acc2[gi] = 0ull;
#pragma unroll 2
      for (int p = 0; p < 256; p += 2){
        ull xa = xq[p*33 + lane];
        ull xb = xq[(p+1)*33 + lane];
#pragma unroll
        for (int gi = 0; gi < 4; gi++){
          ulonglong2 wv = *(const ulonglong2*)(w_ih1 + (size_t)(gi*512 + jC)*512 + (p<<1));
          acc2[gi] = ff2(wv.x, xa, acc2[gi]);
          acc2[gi] = ff2(wv.y, xb, acc2[gi]);
        }
      }
      float gv[4];
#pragma unroll
      for (int gi = 0; gi < 4; gi++){
        int col = gi*512 + jC;
        gv[gi] = upsum(acc2[gi]) + __ldcg(g_p + (size_t)(2048 + col)*32 + lane)
               + b_ih1[col] + b_hh1[col];
      }
      float cp = (t == 0) ? c0in[16384 + lane*512 + jC] : creg1;
      float cn = sigf(gv[1])*cp + sigf(gv[0])*tanhf(gv[2]);
      creg1 = cn;
      float hn = sigf(gv[3])*tanhf(cn);
      g_h1s[lane*512 + jC] = hn;
      g_q[lane*512 + jC] = hn;
      g_outs[(size_t)(t*32 + lane)*512 + jC] = hn;
      if (t == 63) g_cfin[16384 + lane*512 + jC] = cn;
    }
    gsync(gen);  // barrier 3
  }
}

// ---------------- final log-probs ----------------
__global__ void k_final(const int* __restrict__ target, const float* __restrict__ head_w,
                        const float* __restrict__ t1_w2, const float* __restrict__ t2_w2,
                        float* out, int out_size){
  int warp = threadIdx.x >> 5, lane = threadIdx.x & 31;
  int n = blockIdx.x*8 + warp;
  if (n >= NR) return;
  int b = n & 31, s = n >> 5;
  int tgt = target[b*64 + s];
  const float* x = g_outs + (size_t)n*512;
  int csel = (tgt < C1d) ? tgt : ((tgt < C2d) ? C1d : C1d+1);
  float d = 0.f;
  const float* hw = head_w + (size_t)csel*512;
  for (int k = lane; k < 512; k += 32) d = fmaf(x[k], hw[k], d);
  d = wred(d);
  float lp;
  if (tgt < C1d){
    lp = d - g_lse[0][n];
  } else if (tgt < C2d){
    const float* h1 = g_hid1 + (size_t)n*128;
    const float* w2 = t1_w2 + (size_t)(tgt - C1d)*128;
    float d2 = 0.f;
    for (int k = lane; k < 128; k += 32) d2 = fmaf(h1[k], w2[k], d2);
    d2 = wred(d2);
    lp = (d - g_lse[0][n]) + (d2 - g_lse[1][n]);
  } else {
    const float* h2 = g_hid2 + (size_t)n*32;
    const float* w2 = t2_w2 + (size_t)(tgt - C2d)*32;
    float d2 = h2[lane]*w2[lane];
    d2 = wred(d2);
    lp = (d - g_lse[0][n]) + (d2 - g_lse[2][n]);
  }
  if (lane == 0){
    g_outlp[n] = lp;
    if (n < out_size) out[n] = lp;
  }
}

__global__ void k_loss(float* out, int out_size){
  __shared__ float sm[256];
  float s = 0.f;
  for (int i = threadIdx.x; i < NR; i += 256) s += g_outlp[i];
  sm[threadIdx.x] = s; __syncthreads();
  for (int o = 128; o; o >>= 1){ if (threadIdx.x < o) sm[threadIdx.x] += sm[threadIdx.x+o]; __syncthreads(); }
  if (threadIdx.x == 0 && O_LOSS < out_size) out[O_LOSS] = -sm[0]/(float)NR;
}

__global__ void k_copy(float* out, int out_size){
  int idx = blockIdx.x*256 + threadIdx.x + O_OUTS;
  if (idx >= out_size || idx >= O_TOT) return;
  float v;
  if (idx < O_HF) v = g_outs[idx - O_OUTS];
  else if (idx < O_CF){ int o = idx - O_HF; v = (o < 16384) ? g_h0s[o] : g_h1s[o - 16384]; }
  else if (idx < O_ATTN) v = g_cfin[idx - O_CF];
  else if (idx < O_COV) v = g_attn[idx - O_ATTN];
  else v = g_cov[idx - O_COV];
  out[idx] = v;
}

// ---------------- launch ----------------
extern "C" void kernel_launch(void* const* d_in, const int* in_sizes, int n_in,
                              void* d_out, int out_size){
  const int*   inputs = (const int*)d_in[0];
  const int*   topics = (const int*)d_in[1];
  const float* output = (const float*)d_in[2];
  const float* h0     = (const float*)d_in[3];
  const float* c0     = (const float*)d_in[4];
  const float* mask   = (const float*)d_in[5];
  const int*   target = (const int*)d_in[6];
  const float* cover  = (const float*)d_in[7];
  const float* emb_w  = (const float*)d_in[8];
  const float* Uf_w   = (const float*)d_in[9];
  const float* Ua_w   = (const float*)d_in[10];
  const float* Wa_w   = (const float*)d_in[11];
  const float* va_w   = (const float*)d_in[12];
  const float* va_b   = (const float*)d_in[13];
  const float* w_ih0  = (const float*)d_in[14];
  const float* w_hh0  = (const float*)d_in[15];
  const float* b_ih0  = (const float*)d_in[16];
  const float* b_hh0  = (const float*)d_in[17];
  const float* w_ih1  = (const float*)d_in[18];
  const float* w_hh1  = (const float*)d_in[19];
  const float* b_ih1  = (const float*)d_in[20];
  const float* b_hh1  = (const float*)d_in[21];
  const float* head_w = (const float*)d_in[22];
  const float* t1_w1  = (const float*)d_in[23];
  const float* t1_w2  = (const float*)d_in[24];
  const float* t2_w1  = (const float*)d_in[25];
  const float* t2_w2  = (const float*)d_in[26];
  float* out = (float*)d_out;

  float *pWaT, *pWaP, *pTe, *pProj, *pEmbp, *pT0, *pOuts, *pH1, *pH2;
  int* pRid;
  cudaGetSymbolAddress((void**)&pWaT, g_WaT);
  cudaGetSymbolAddress((void**)&pWaP, g_WaP);
  cudaGetSymbolAddress((void**)&pTe,  g_topics_e);
  cudaGetSymbolAddress((void**)&pProj,g_proj);
  cudaGetSymbolAddress((void**)&pEmbp,g_embpart);
  cudaGetSymbolAddress((void**)&pT0,  g_T0);
  cudaGetSymbolAddress((void**)&pOuts,g_outs);
  cudaGetSymbolAddress((void**)&pH1,  g_hid1);
  cudaGetSymbolAddress((void**)&pH2,  g_hid2);
  cudaGetSymbolAddress((void**)&pRid, g_rowidx);

  cudaFuncSetAttribute(k_recur, cudaFuncAttributeMaxDynamicSharedMemorySize, 69632);

  k_init<<<320, 256>>>(inputs, topics, output, h0, cover, emb_w);
  k_prepwa<<<1024, 256>>>(Wa_w);
  k_prepwh<<<4096, 256>>>(w_hh0, w_hh1);
  k_phi<<<20, 256>>>(Uf_w, mask);
  // Wa powers: WaP[i+1] = WaP[i] @ Wa
  for (int i = 0; i < 4; i++)
    k_mm128<false><<<dim3(4,4), 256>>>(pWaP + (size_t)i*HH, 512, pWaT, 512,
                                       pWaP + (size_t)(i+1)*HH, 512, 512, 512, 512, nullptr);
  // proj_keys = topics_e @ Ua^T
  k_mm128<false><<<dim3(4,2), 256>>>(pTe, 512, Ua_w, 512, pProj, 512, 160, 512, 512, nullptr);
  k_projT<<<(2560*32+255)/256, 256>>>();
  // embpart = gathered emb @ w_ih0[:, :512]^T (+ biases)
  k_mm128<false><<<dim3(16,16), 256>>>(emb_w, 512, w_ih0, 1024, pEmbp, 2048, 2048, 2048, 512, pRid);
  k_bias0<<<2048, 256>>>(b_ih0, b_hh0);
  // T0 = w_ih0[:, 512:] @ topics_e^T
  k_mm128<false><<<dim3(2,16), 256>>>(w_ih0 + 512, 1024, pTe, 512, pT0, 160, 2048, 160, 512, nullptr);
  // recurrence
  k_recur<<<GRID, 256, 67584>>>(w_ih1, b_ih1, b_hh1, va_w, va_b, c0);
  // adaptive softmax head
  k_mm128<false><<<dim3(1,16), 256>>>(pOuts, 512, t1_w1, 512, pH1, 128, 2048, 128, 512, nullptr);
  k_mm128<false><<<dim3(1,16), 256>>>(pOuts, 512, t2_w1, 512, pH2, 32, 2048, 32, 512, nullptr);
  k_mm128<true><<<dim3(20,16), 256>>>(pOuts, 512, head_w, 512, nullptr, 0, 2048, 2502, 512, nullptr);
  k_lsemerge<<<2048, 128>>>(20, 0);
  k_mm128<true><<<dim3(59,16), 256>>>(pH1, 128, t1_w2, 128, nullptr, 0, 2048, 7500, 128, nullptr);
  k_lsemerge<<<2048, 128>>>(59, 1);
  k_mm128<true><<<dim3(313,16), 256>>>(pH2, 32, t2_w2, 32, nullptr, 0, 2048, 40000, 32, nullptr);
  k_lsemerge<<<2048, 128>>>(313, 2);
  k_final<<<256, 256>>>(target, head_w, t1_w2, t2_w2, out, out_size);
  k_loss<<<1, 256>>>(out, out_size);
  k_copy<<<(O_TOT - O_OUTS + 255)/256, 256>>>(out, out_size);
}